// round 1
// baseline (speedup 1.0000x reference)
#include <cuda_runtime.h>
#include <cuda_bf16.h>

// Problem constants
#define NPTS   1048576
#define CIN    64
#define COUT   96
#define NB     4
// segment counts: k=2 -> 64^3 per batch, k=4 -> 32^3, k=8 -> 16^3
#define NSEG2  1048576   // 4 * 64*64*64
#define NSEG4  131072    // 4 * 32*32*32
#define NSEG8  16384     // 4 * 16*16*16

// ---------------- static device scratch (allocation-free rule) ----------------
__device__ float g_sums2[(long)NSEG2 * 64];   // 268 MB
__device__ float g_cnt2[NSEG2];
__device__ float g_sums4[(long)NSEG4 * 64];   // 33.5 MB
__device__ float g_cnt4[NSEG4];
__device__ float g_sums8[(long)NSEG8 * 64];   // 4 MB
__device__ float g_cnt8[NSEG8];
__device__ float g_base0[NB * COUT];          // b + W0 @ mean0 per batch
__device__ float g_Z8[(long)NSEG8 * COUT];    // 6.3 MB
__device__ float g_Z4[(long)NSEG4 * COUT];    // 50 MB
__device__ float g_Z2[(long)NSEG2 * COUT];    // 403 MB
__device__ int   g_seg2[NPTS];
__device__ int   g_active[NSEG2];
__device__ int   g_nactive;

// ---------------- helpers ----------------
__device__ __forceinline__ void red_add_v4(float* addr, float4 v) {
    asm volatile("red.global.add.v4.f32 [%0], {%1, %2, %3, %4};"
                 :: "l"(addr), "f"(v.x), "f"(v.y), "f"(v.z), "f"(v.w)
                 : "memory");
}

// ---------------- kernel 1: zero scratch ----------------
__global__ void zero_kernel() {
    long tid = (long)blockIdx.x * blockDim.x + threadIdx.x;
    long stride = (long)gridDim.x * blockDim.x;
    float4 z = make_float4(0.f, 0.f, 0.f, 0.f);
    float4* s2 = (float4*)g_sums2;
    for (long i = tid; i < (long)NSEG2 * 16; i += stride) s2[i] = z;
    float4* s4 = (float4*)g_sums4;
    for (long i = tid; i < (long)NSEG4 * 16; i += stride) s4[i] = z;
    float4* s8 = (float4*)g_sums8;
    for (long i = tid; i < (long)NSEG8 * 16; i += stride) s8[i] = z;
    float4* c2 = (float4*)g_cnt2;
    for (long i = tid; i < NSEG2 / 4; i += stride) c2[i] = z;
    float4* c4 = (float4*)g_cnt4;
    for (long i = tid; i < NSEG4 / 4; i += stride) c4[i] = z;
    float4* c8 = (float4*)g_cnt8;
    for (long i = tid; i < NSEG8 / 4; i += stride) c8[i] = z;
    if (tid == 0) g_nactive = 0;
}

// ---------------- kernel 2: scatter point features into 3 pyramid levels ----------------
__global__ __launch_bounds__(256) void scatter_kernel(
    const float4* __restrict__ feats4,
    const int* __restrict__ coords,
    const int* __restrict__ batch)
{
    int p = blockIdx.x * 256 + threadIdx.x;
    if (p >= NPTS) return;
    int x = coords[3 * p + 0];
    int y = coords[3 * p + 1];
    int z = coords[3 * p + 2];
    int b = batch[p];

    int s2 = (b << 18) | ((x >> 1) << 12) | ((y >> 1) << 6) | (z >> 1);
    int s4 = (b << 15) | ((x >> 2) << 10) | ((y >> 2) << 5) | (z >> 2);
    int s8 = (b << 12) | ((x >> 3) << 8)  | ((y >> 3) << 4) | (z >> 3);

    g_seg2[p] = s2;

    float old = atomicAdd(&g_cnt2[s2], 1.0f);
    if (old == 0.0f) {
        int k = atomicAdd(&g_nactive, 1);
        g_active[k] = s2;
    }
    atomicAdd(&g_cnt4[s4], 1.0f);
    atomicAdd(&g_cnt8[s8], 1.0f);

    float* p2 = &g_sums2[(long)s2 * 64];
    float* p4 = &g_sums4[(long)s4 * 64];
    float* p8 = &g_sums8[(long)s8 * 64];
    const float4* f = feats4 + (long)p * 16;
#pragma unroll
    for (int i = 0; i < 16; i++) {
        float4 v = f[i];
        red_add_v4(p2 + 4 * i, v);
        red_add_v4(p4 + 4 * i, v);
        red_add_v4(p8 + 4 * i, v);
    }
}

// ---------------- kernel 3: level-0 (global per-batch) reduce + base projection ----------------
// base0[b] = bias + W[:, 0:64] @ mean0[b], where sum0 = sum over this batch's k=8 rows.
__global__ __launch_bounds__(256) void l0_kernel(
    const float* __restrict__ W, const float* __restrict__ bias)
{
    int b = blockIdx.x;
    int tid = threadIdx.x;
    __shared__ float sm[4][64];
    __shared__ float smean[64];
    __shared__ float scnt[256];

    int c = tid & 63, g = tid >> 6;
    const float* base = g_sums8 + (long)b * 4096 * 64;
    float acc = 0.f;
    for (int s = g; s < 4096; s += 4) acc += base[s * 64 + c];
    sm[g][c] = acc;

    float ca = 0.f;
    for (int s = tid; s < 4096; s += 256) ca += g_cnt8[b * 4096 + s];
    scnt[tid] = ca;
    __syncthreads();

    for (int off = 128; off > 0; off >>= 1) {
        if (tid < off) scnt[tid] += scnt[tid + off];
        __syncthreads();
    }
    if (tid < 64) {
        smean[tid] = (sm[0][tid] + sm[1][tid] + sm[2][tid] + sm[3][tid])
                   / fmaxf(scnt[0], 1.0f);
    }
    __syncthreads();
    if (tid < 96) {
        float a = bias[tid];
        const float* wr = W + tid * 256;  // global block = cols [0,64)
#pragma unroll 8
        for (int k = 0; k < 64; k++) a += wr[k] * smean[k];
        g_base0[b * COUT + tid] = a;
    }
}

// ---------------- kernel 4: pyramid transform Z_level = Z_parent + W_level @ mean_level ----------------
// LEVEL in {8,4,2}. Block = 128 threads, tile = 32 segments x 96 outputs, K = 64.
template <int LEVEL>
__global__ __launch_bounds__(128) void transform_kernel(const float* __restrict__ W)
{
    __shared__ float sh_W[96 * 65];   // [out][k], padded
    __shared__ float sh_m[64 * 36];   // [k][slot], padded, 16B-aligned rows
    __shared__ int   sh_sid[32];

    int tid  = threadIdx.x;
    int base = blockIdx.x * 32;
    int nact = 0;
    if (LEVEL == 2) {
        nact = g_nactive;
        if (base >= nact) return;
    }

    if (tid < 32) {
        int s;
        if (LEVEL == 2) s = (base + tid < nact) ? g_active[base + tid] : -1;
        else            s = base + tid;
        sh_sid[tid] = s;
    }

    const int WOFS = (LEVEL == 2) ? 64 : (LEVEL == 4) ? 128 : 192;
    for (int j = tid; j < 96 * 64; j += 128) {
        int o = j >> 6, c = j & 63;
        sh_W[o * 65 + c] = W[o * 256 + WOFS + c];
    }
    __syncthreads();

    const float* SUMS = (LEVEL == 2) ? g_sums2 : (LEVEL == 4) ? g_sums4 : g_sums8;
    const float* CNT  = (LEVEL == 2) ? g_cnt2  : (LEVEL == 4) ? g_cnt4  : g_cnt8;

    // stage means (transposed into sh_m[k][slot]), 16 threads per segment row (coalesced)
    for (int it = tid; it < 512; it += 128) {
        int slot = it >> 4, kc = it & 15;
        int s = sh_sid[slot];
        float4 v = make_float4(0.f, 0.f, 0.f, 0.f);
        float inv = 0.f;
        if (s >= 0) {
            v = *(const float4*)&SUMS[(long)s * 64 + kc * 4];
            inv = 1.0f / fmaxf(CNT[s], 1.0f);
        }
        sh_m[(4 * kc + 0) * 36 + slot] = v.x * inv;
        sh_m[(4 * kc + 1) * 36 + slot] = v.y * inv;
        sh_m[(4 * kc + 2) * 36 + slot] = v.z * inv;
        sh_m[(4 * kc + 3) * 36 + slot] = v.w * inv;
    }
    __syncthreads();

    int rt = tid >> 4, ct = tid & 15;
    int r0 = rt * 4, c0 = ct * 6;

    float acc[4][6];
#pragma unroll
    for (int i = 0; i < 4; i++)
#pragma unroll
        for (int j = 0; j < 6; j++) acc[i][j] = 0.f;

#pragma unroll 8
    for (int k = 0; k < 64; k++) {
        float4 m = *(const float4*)&sh_m[k * 36 + r0];
        float mv[4] = {m.x, m.y, m.z, m.w};
        float w[6];
#pragma unroll
        for (int j = 0; j < 6; j++) w[j] = sh_W[(c0 + j) * 65 + k];
#pragma unroll
        for (int i = 0; i < 4; i++)
#pragma unroll
            for (int j = 0; j < 6; j++) acc[i][j] = fmaf(mv[i], w[j], acc[i][j]);
    }

    // epilogue: add parent's projected vector, write Z_level
#pragma unroll
    for (int i = 0; i < 4; i++) {
        int s = sh_sid[r0 + i];
        if (s < 0) continue;
        const float* prev;
        float* Zout;
        if (LEVEL == 8) {
            prev = &g_base0[(s >> 12) * COUT];
            Zout = g_Z8;
        } else if (LEVEL == 4) {
            int bb = s >> 15, xx = (s >> 10) & 31, yy = (s >> 5) & 31, zz = s & 31;
            int s8 = (bb << 12) | ((xx >> 1) << 8) | ((yy >> 1) << 4) | (zz >> 1);
            prev = &g_Z8[(long)s8 * COUT];
            Zout = g_Z4;
        } else {
            int bb = s >> 18, xx = (s >> 12) & 63, yy = (s >> 6) & 63, zz = s & 63;
            int s4 = (bb << 15) | ((xx >> 1) << 10) | ((yy >> 1) << 5) | (zz >> 1);
            prev = &g_Z4[(long)s4 * COUT];
            Zout = g_Z2;
        }
        float* dst = &Zout[(long)s * COUT + c0];
#pragma unroll
        for (int j = 0; j < 6; j++) dst[j] = acc[i][j] + prev[c0 + j];
    }
}

// ---------------- kernel 5: gather out[n] = Z2[seg2(n)] ----------------
__global__ __launch_bounds__(256) void gather_kernel(float4* __restrict__ out4)
{
    int i = blockIdx.x * 256 + threadIdx.x;  // over NPTS * 24 float4 chunks
    if (i >= NPTS * 24) return;
    int p = i / 24;
    int q = i - p * 24;
    int s = g_seg2[p];
    out4[i] = ((const float4*)g_Z2)[(long)s * 24 + q];
}

// ---------------- launcher ----------------
extern "C" void kernel_launch(void* const* d_in, const int* in_sizes, int n_in,
                              void* d_out, int out_size)
{
    const float* feats  = (const float*)d_in[0];
    const int*   coords = (const int*)d_in[1];
    const int*   batch  = (const int*)d_in[2];
    const float* W      = (const float*)d_in[3];
    const float* bias   = (const float*)d_in[4];

    zero_kernel<<<2048, 256>>>();
    scatter_kernel<<<NPTS / 256, 256>>>((const float4*)feats, coords, batch);
    l0_kernel<<<NB, 256>>>(W, bias);
    transform_kernel<8><<<NSEG8 / 32, 128>>>(W);
    transform_kernel<4><<<NSEG4 / 32, 128>>>(W);
    transform_kernel<2><<<NSEG2 / 32, 128>>>(W);
    gather_kernel<<<(NPTS * 24) / 256, 256>>>((float4*)d_out);
}